// round 6
// baseline (speedup 1.0000x reference)
#include <cuda_runtime.h>
#include <cstdint>
#include <cstddef>

#define B_  4
#define S_  2048
#define D_  512
#define H_  8
#define DEPTH 64
#define BH  (B_*H_)

// fragment-permuted k-slot: 8 consecutive u32 hold a thread's a0/a2 (or b0/b1)
// for four consecutive k8 steps.
#define PERM32(c) ((((c)&3)<<3) | (((c)>>2)&7))
#define PERM64(c) ((((c)>>5)<<5) | (((c)&3)<<3) | (((c)>>2)&7))

// ---------------- scratch ----------------
__device__ float g_Q[(size_t)BH*S_*DEPTH];
__device__ float g_K[(size_t)BH*S_*DEPTH];    // K'' = k@Wk + pos@Wd
__device__ float g_V[(size_t)BH*S_*DEPTH];
__device__ float g_ctx[(size_t)B_*S_*D_];
__device__ float g_rsinv[(size_t)BH*S_];

// ---------------- tf32 helpers ----------------
__device__ __forceinline__ uint32_t f2tf(float x){
    uint32_t u; asm("cvt.rna.tf32.f32 %0, %1;" : "=r"(u) : "f"(x)); return u;
}
__device__ __forceinline__ void mma8(float c[4], uint32_t a0,uint32_t a1,uint32_t a2,uint32_t a3,
                                     uint32_t b0,uint32_t b1){
    asm volatile("mma.sync.aligned.m16n8k8.row.col.f32.tf32.tf32.f32 "
        "{%0,%1,%2,%3}, {%4,%5,%6,%7}, {%8,%9}, {%0,%1,%2,%3};"
        : "+f"(c[0]),"+f"(c[1]),"+f"(c[2]),"+f"(c[3])
        : "r"(a0),"r"(a1),"r"(a2),"r"(a3),"r"(b0),"r"(b1));
}

// ---------------- projection / output GEMM ----------------
// As: [128 m][36] slots PERM32(k).  Bs: [64 n][36] slots PERM32(k) (B stored transposed).
__device__ __forceinline__ void gemm_core(
    const float* __restrict__ A1, const float* __restrict__ B1, const float* __restrict__ bias1,
    const float* __restrict__ A2, const float* __restrict__ B2, const float* __restrict__ bias2,
    float* __restrict__ C, int split, int m0, int n0,
    uint32_t (*As)[36], uint32_t (*Bs)[36])
{
    int tid = threadIdx.x;
    int lane = tid & 31, wid = tid >> 5;
    int g = lane >> 2, tg = lane & 3;
    int wm = wid & 3, wn = wid >> 2;          // 4x2 warps -> CTA tile 128x64

    float acc[2][4][4];
    #pragma unroll
    for (int i=0;i<2;i++)
        #pragma unroll
        for (int j=0;j<4;j++)
            #pragma unroll
            for (int r=0;r<4;r++) acc[i][j][r]=0.f;

    const int ntile = A2 ? 32 : 16;
    float4 ra[4]; float4 rb[2];
    auto ldg_tile = [&](int t){
        const float* A  = (t >= 16) ? A2 : A1;
        const float* Bm = (t >= 16) ? B2 : B1;
        int k0 = (t & 15) * 32;
        #pragma unroll
        for (int i=0;i<4;i++){
            int e = tid + i*256; int r = e>>3, c = (e&7)*4;
            ra[i] = *(const float4*)(A + (size_t)(m0+r)*512 + k0 + c);
        }
        #pragma unroll
        for (int i=0;i<2;i++){
            int e = tid + i*256; int r = e>>4, c = (e&15)*4;
            rb[i] = *(const float4*)(Bm + (size_t)(k0+r)*512 + n0 + c);
        }
    };

    ldg_tile(0);
    for (int t = 0; t < ntile; t++){
        // stage A: row r, k = c0..c0+3 -> slots j*8 + (c0>>2)
        #pragma unroll
        for (int i=0;i<4;i++){
            int e = tid + i*256; int r = e>>3; int q = e&7;  // c0 = q*4
            As[r][q     ] = f2tf(ra[i].x);
            As[r][q +  8] = f2tf(ra[i].y);
            As[r][q + 16] = f2tf(ra[i].z);
            As[r][q + 24] = f2tf(ra[i].w);
        }
        // stage B transposed: global row k, cols n0..n0+3 -> Bs[n][PERM32(k)]
        #pragma unroll
        for (int i=0;i<2;i++){
            int e = tid + i*256; int k = e>>4; int n = (e&15)*4;
            int s = PERM32(k);
            Bs[n  ][s] = f2tf(rb[i].x);
            Bs[n+1][s] = f2tf(rb[i].y);
            Bs[n+2][s] = f2tf(rb[i].z);
            Bs[n+3][s] = f2tf(rb[i].w);
        }
        __syncthreads();
        if (t+1 < ntile) ldg_tile(t+1);

        uint32_t ar[2][2][8];
        #pragma unroll
        for (int mi=0;mi<2;mi++)
            #pragma unroll
            for (int rr=0;rr<2;rr++){
                const uint32_t* p = &As[wm*32 + mi*16 + g + rr*8][tg*8];
                *(uint4*)&ar[mi][rr][0] = *(const uint4*)p;
                *(uint4*)&ar[mi][rr][4] = *(const uint4*)(p+4);
            }
        #pragma unroll
        for (int ni=0;ni<4;ni++){
            uint32_t br[8];
            const uint32_t* p = &Bs[wn*32 + ni*8 + g][tg*8];
            *(uint4*)&br[0] = *(const uint4*)p;
            *(uint4*)&br[4] = *(const uint4*)(p+4);
            #pragma unroll
            for (int q=0;q<4;q++){
                mma8(acc[0][ni], ar[0][0][2*q], ar[0][1][2*q], ar[0][0][2*q+1], ar[0][1][2*q+1],
                     br[2*q], br[2*q+1]);
                mma8(acc[1][ni], ar[1][0][2*q], ar[1][1][2*q], ar[1][0][2*q+1], ar[1][1][2*q+1],
                     br[2*q], br[2*q+1]);
            }
        }
        __syncthreads();
    }

    #pragma unroll
    for (int mi=0;mi<2;mi++)
        #pragma unroll
        for (int ni=0;ni<4;ni++)
            #pragma unroll
            for (int half=0; half<2; half++){
                int row = m0 + wm*32 + mi*16 + g + half*8;
                int col = n0 + wn*32 + ni*8 + tg*2;
                float b0v = bias1[col]   + (bias2 ? bias2[col]   : 0.f);
                float b1v = bias1[col+1] + (bias2 ? bias2[col+1] : 0.f);
                float v0 = acc[mi][ni][half*2+0] + b0v;
                float v1 = acc[mi][ni][half*2+1] + b1v;
                size_t idx;
                if (split){
                    int b = row >> 11, s = row & 2047;
                    int h = col >> 6,  d = col & 63;
                    idx = (((size_t)(b*H_ + h))*S_ + s)*DEPTH + d;
                } else {
                    idx = (size_t)row*512 + col;
                }
                *(float2*)(C + idx) = make_float2(v0, v1);
            }
}

__global__ __launch_bounds__(256)
void proj3(const float* q, const float* k, const float* pe, const float* v,
           const float* Wq, const float* Wk, const float* Wv, const float* Wd,
           const float* bq, const float* bk, const float* bv, const float* bd,
           float* Qp, float* Kp, float* Vp)
{
    __shared__ uint32_t As[128][36];
    __shared__ uint32_t Bs[64][36];
    int m0 = blockIdx.y*128, n0 = blockIdx.x*64;
    if (blockIdx.z == 0)
        gemm_core(q, Wq, bq, nullptr,nullptr,nullptr, Qp, 1, m0,n0, As,Bs);
    else if (blockIdx.z == 1)
        gemm_core(k, Wk, bk, pe, Wd, bd, Kp, 1, m0,n0, As,Bs);
    else
        gemm_core(v, Wv, bv, nullptr,nullptr,nullptr, Vp, 1, m0,n0, As,Bs);
}

__global__ __launch_bounds__(256)
void gemm_out(const float* __restrict__ A, const float* __restrict__ Bm,
              const float* __restrict__ bias, float* __restrict__ C)
{
    __shared__ uint32_t As[128][36];
    __shared__ uint32_t Bs[64][36];
    gemm_core(A, Bm, bias, nullptr,nullptr,nullptr, C, 0,
              blockIdx.y*128, blockIdx.x*64, As, Bs);
}

// ---------------- attention fragment helpers ----------------
// A rows from Xs[128][68] (slots PERM64), B rows from Ys[64][68] (n-major, slots PERM64)
#define LOAD_A8(dst, Xs, row, h, tg) { \
    const uint32_t* _p = &Xs[row][(h)*32 + (tg)*8]; \
    *(uint4*)&dst[0] = *(const uint4*)_p; \
    *(uint4*)&dst[4] = *(const uint4*)(_p+4); }

// ---------------- pass 1: rowsum of exp(logits) ----------------
__global__ __launch_bounds__(256)
void attn_rowsum(const float* __restrict__ Q, const float* __restrict__ Kp,
                 float* __restrict__ rsinv)
{
    extern __shared__ uint32_t sm1[];
    uint32_t (*Qs)[68] = (uint32_t(*)[68])sm1;                 // 128 x PERM64
    uint32_t (*Ks)[68] = (uint32_t(*)[68])(sm1 + 128*68);      // 64(t) x PERM64(d)
    float *rs = (float*)(sm1 + 128*68 + 64*68);

    int tid = threadIdx.x;
    int lane = tid & 31, wid = tid >> 5;
    int g = lane >> 2, tg = lane & 3;
    int wm = wid & 3, wn = wid >> 2;
    int bh = blockIdx.y;
    int s0 = blockIdx.x * 128;

    const float* Qb = Q  + ((size_t)bh*S_ + s0)*DEPTH;
    const float* Kb = Kp +  (size_t)bh*S_*DEPTH;

    #pragma unroll
    for (int i=0;i<8;i++){
        int e = tid + i*256;
        int r = e>>4, q = e&15;                 // c0 = q*4
        float4 v = *(const float4*)(Qb + (size_t)r*DEPTH + q*4);
        int base = (q>=8)*32 + (q&7);
        Qs[r][base     ] = f2tf(v.x);
        Qs[r][base +  8] = f2tf(v.y);
        Qs[r][base + 16] = f2tf(v.z);
        Qs[r][base + 24] = f2tf(v.w);
    }
    if (tid < 128) rs[tid] = 0.f;
    __syncthreads();

    float4 kr[4];
    auto ldgK = [&](int t0){
        #pragma unroll
        for (int i=0;i<4;i++){
            int e = tid + i*256;
            int r = e>>4, c = (e&15)*4;
            kr[i] = *(const float4*)(Kb + (size_t)(t0+r)*DEPTH + c);
        }
    };
    ldgK(0);

    float rowacc[4] = {0.f,0.f,0.f,0.f};

    for (int t0 = 0; t0 < S_; t0 += 64){
        #pragma unroll
        for (int i=0;i<4;i++){
            int e = tid + i*256;
            int r = e>>4, q = e&15;
            int base = (q>=8)*32 + (q&7);
            Ks[r][base     ] = f2tf(kr[i].x);
            Ks[r][base +  8] = f2tf(kr[i].y);
            Ks[r][base + 16] = f2tf(kr[i].z);
            Ks[r][base + 24] = f2tf(kr[i].w);
        }
        __syncthreads();
        if (t0 + 64 < S_) ldgK(t0 + 64);

        float acc[2][4][4];
        #pragma unroll
        for (int i=0;i<2;i++)
            #pragma unroll
            for (int j=0;j<4;j++)
                #pragma unroll
                for (int r=0;r<4;r++) acc[i][j][r]=0.f;

        #pragma unroll
        for (int h=0;h<2;h++){
            uint32_t ar[2][2][8];
            #pragma unroll
            for (int mi=0;mi<2;mi++)
                #pragma unroll
                for (int rr=0;rr<2;rr++)
                    LOAD_A8(ar[mi][rr], Qs, wm*32+mi*16+g+rr*8, h, tg);
            #pragma unroll
            for (int ni=0;ni<4;ni++){
                uint32_t br[8];
                LOAD_A8(br, Ks, wn*32+ni*8+g, h, tg);
                #pragma unroll
                for (int q=0;q<4;q++){
                    mma8(acc[0][ni], ar[0][0][2*q], ar[0][1][2*q], ar[0][0][2*q+1], ar[0][1][2*q+1],
                         br[2*q], br[2*q+1]);
                    mma8(acc[1][ni], ar[1][0][2*q], ar[1][1][2*q], ar[1][0][2*q+1], ar[1][1][2*q+1],
                         br[2*q], br[2*q+1]);
                }
            }
        }
        #pragma unroll
        for (int mi=0;mi<2;mi++)
            #pragma unroll
            for (int ni=0;ni<4;ni++)
                #pragma unroll
                for (int r2=0;r2<4;r2++)
                    rowacc[mi*2 + (r2>>1)] += __expf(acc[mi][ni][r2]*0.125f);
        __syncthreads();
    }

    #pragma unroll
    for (int i=0;i<4;i++){
        float v = rowacc[i];
        v += __shfl_xor_sync(0xffffffffu, v, 1);
        v += __shfl_xor_sync(0xffffffffu, v, 2);
        if (tg == 0){
            int row = wm*32 + (i>>1)*16 + g + (i&1)*8;
            atomicAdd(&rs[row], v);
        }
    }
    __syncthreads();
    if (tid < 128) rsinv[(size_t)bh*S_ + s0 + tid] = 1.0f / rs[tid];
}

// ---------------- pass 2: attn write + ctx = attn @ V ----------------
__global__ __launch_bounds__(256)
void attn_pv(const float* __restrict__ Q, const float* __restrict__ Kp,
             const float* __restrict__ V, const float* __restrict__ rsinv,
             float* __restrict__ attn, float* __restrict__ ctx)
{
    extern __shared__ uint32_t sm2[];
    uint32_t (*Qs)[68] = (uint32_t(*)[68])sm2;                          // 128 x PERM64(d)
    uint32_t (*Ks)[68] = (uint32_t(*)[68])(sm2 + 128*68);               // 64(t) x PERM64(d)
    uint32_t (*Ps)[68] = (uint32_t(*)[68])(sm2 + 128*68 + 64*68);       // 128 x PERM64(t)
    uint32_t (*Vs)[68] = (uint32_t(*)[68])(sm2 + 128*68 + 64*68 + 128*68); // 64(d) x PERM64(t)
    float *rsv = (float*)(sm2 + 128*68 + 64*68 + 128*68 + 64*68);

    int tid = threadIdx.x;
    int lane = tid & 31, wid = tid >> 5;
    int g = lane >> 2, tg = lane & 3;
    int wm = wid & 3, wn = wid >> 2;
    int bh = blockIdx.y;
    int s0 = blockIdx.x * 128;

    const float* Qb = Q  + ((size_t)bh*S_ + s0)*DEPTH;
    const float* Kb = Kp +  (size_t)bh*S_*DEPTH;
    const float* Vb = V  +  (size_t)bh*S_*DEPTH;
    float* attn_strip = attn + ((size_t)bh*S_ + s0)*S_;

    #pragma unroll
    for (int i=0;i<8;i++){
        int e = tid + i*256;
        int r = e>>4, q = e&15;
        float4 v = *(const float4*)(Qb + (size_t)r*DEPTH + q*4);
        int base = (q>=8)*32 + (q&7);
        Qs[r][base     ] = f2tf(v.x);
        Qs[r][base +  8] = f2tf(v.y);
        Qs[r][base + 16] = f2tf(v.z);
        Qs[r][base + 24] = f2tf(v.w);
    }
    if (tid < 128) rsv[tid] = rsinv[(size_t)bh*S_ + s0 + tid];
    __syncthreads();

    float4 kr[4], vr[4];
    auto ldgKV = [&](int t0){
        #pragma unroll
        for (int i=0;i<4;i++){
            int e = tid + i*256;
            int r = e>>4, c = (e&15)*4;
            kr[i] = *(const float4*)(Kb + (size_t)(t0+r)*DEPTH + c);
            vr[i] = *(const float4*)(Vb + (size_t)(t0+r)*DEPTH + c);
        }
    };
    ldgKV(0);

    float octx[2][4][4];
    #pragma unroll
    for (int i=0;i<2;i++)
        #pragma unroll
        for (int j=0;j<4;j++)
            #pragma unroll
            for (int r=0;r<4;r++) octx[i][j][r]=0.f;

    for (int t0 = 0; t0 < S_; t0 += 64){
        #pragma unroll
        for (int i=0;i<4;i++){
            int e = tid + i*256;
            int r = e>>4, q = e&15;           // K: row t=r, k=d ; V: transpose -> Vs[d][PERM64(t)]
            int base = (q>=8)*32 + (q&7);
            Ks[r][base     ] = f2tf(kr[i].x);
            Ks[r][base +  8] = f2tf(kr[i].y);
            Ks[r][base + 16] = f2tf(kr[i].z);
            Ks[r][base + 24] = f2tf(kr[i].w);
            int d0 = q*4;
            int st = PERM64(r);
            Vs[d0  ][st] = f2tf(vr[i].x);
            Vs[d0+1][st] = f2tf(vr[i].y);
            Vs[d0+2][st] = f2tf(vr[i].z);
            Vs[d0+3][st] = f2tf(vr[i].w);
        }
        __syncthreads();
        if (t0 + 64 < S_) ldgKV(t0 + 64);

        float acc[2][4][4];
        #pragma unroll
        for (int i=0;i<2;i++)
            #pragma unroll
            for (int j=0;j<4;j++)
                #pragma unroll
                for (int r=0;r<4;r++) acc[i][j][r]=0.f;

        // logits = Q @ K''^T
        #pragma unroll
        for (int h=0;h<2;h++){
            uint32_t ar[2][2][8];
            #pragma unroll
            for (int mi=0;mi<2;mi++)
                #pragma unroll
                for (int rr=0;rr<2;rr++)
                    LOAD_A8(ar[mi][rr], Qs, wm*32+mi*16+g+rr*8, h, tg);
            #pragma unroll
            for (int ni=0;ni<4;ni++){
                uint32_t br[8];
                LOAD_A8(br, Ks, wn*32+ni*8+g, h, tg);
                #pragma unroll
                for (int q=0;q<4;q++){
                    mma8(acc[0][ni], ar[0][0][2*q], ar[0][1][2*q], ar[0][0][2*q+1], ar[0][1][2*q+1],
                         br[2*q], br[2*q+1]);
                    mma8(acc[1][ni], ar[1][0][2*q], ar[1][1][2*q], ar[1][0][2*q+1], ar[1][1][2*q+1],
                         br[2*q], br[2*q+1]);
                }
            }
        }

        // p = exp(l/8) / rowsum ; write attn + stage tf32 P (PERM64 layout)
        #pragma unroll
        for (int mi=0;mi<2;mi++){
            int r0 = wm*32 + mi*16 + g;
            float inv0 = rsv[r0], inv1 = rsv[r0+8];
            #pragma unroll
            for (int ni=0;ni<4;ni++){
                acc[mi][ni][0] = __expf(acc[mi][ni][0]*0.125f)*inv0;
                acc[mi][ni][1] = __expf(acc[mi][ni][1]*0.125f)*inv0;
                acc[mi][ni][2] = __expf(acc[mi][ni][2]*0.125f)*inv1;
                acc[mi][ni][3] = __expf(acc[mi][ni][3]*0.125f)*inv1;
            }
        }
        #pragma unroll
        for (int mi=0;mi<2;mi++)
            #pragma unroll
            for (int ni=0;ni<4;ni++)
                #pragma unroll
                for (int half=0; half<2; half++){
                    int rloc = wm*32 + mi*16 + g + half*8;
                    int c0 = wn*32 + ni*8 + tg*2;
                    float2 v2 = make_float2(acc[mi][ni][half*2], acc[mi][ni][half*2+1]);
                    Ps[rloc][PERM64(c0)  ] = f2tf(v2.x);
                    Ps[rloc][PERM64(c0+1)] = f2tf(v2.y);
                    *(float2*)(attn_strip + (size_t)rloc*S_ + t0 + c0) = v2;
                }
        __syncthreads();   // P,V complete before PV mma

        // ctx_un += P @ V   (A = Ps rows, B = Vs rows d)
        #pragma unroll
        for (int h=0;h<2;h++){
            uint32_t ar[2][2][8];
            #pragma unroll
            for (int mi=0;mi<2;mi++)
                #pragma unroll
                for (int rr=0;rr<2;rr++)
                    LOAD_A8(ar[mi][rr], Ps, wm*32+mi*16+g+rr*8, h, tg);
            #pragma unroll
            for (int ni=0;ni<4;ni++){
                uint32_t br[8];
                LOAD_A8(br, Vs, wn*32+ni*8+g, h, tg);
                #pragma unroll
                for (int q=0;q<4;q++){
                    mma8(octx[0][ni], ar[0][0][2*q], ar[0][1][2*q], ar[0][0][2*q+1], ar[0][1][2*q+1],
                         br[2*q], br[2*q+1]);
                    mma8(octx[1][ni], ar[1][0][2*q], ar[1][1][2*q], ar[1][0][2*q+1], ar[1][1][2*q+1],
                         br[2*q], br[2*q+1]);
                }
            }
        }
        __syncthreads();
    }

    // write ctx in (B,S,D) layout (already normalized: P was normalized)
    int b = bh >> 3, h2 = bh & 7;
    #pragma unroll
    for (int mi=0;mi<2;mi++)
        #pragma unroll
        for (int ni=0;ni<4;ni++)
            #pragma unroll
            for (int half=0; half<2; half++){
                int row = s0 + wm*32 + mi*16 + g + half*8;
                int col = h2*64 + wn*32 + ni*8 + tg*2;
                float2 v2 = make_float2(octx[mi][ni][half*2], octx[mi][ni][half*2+1]);
                *(float2*)(ctx + ((size_t)b*S_ + row)*D_ + col) = v2;
            }
}

// ---------------- launch ----------------
extern "C" void kernel_launch(void* const* d_in, const int* in_sizes, int n_in,
                              void* d_out, int out_size)
{
    const float* q   = (const float*)d_in[0];
    const float* k   = (const float*)d_in[1];
    const float* v   = (const float*)d_in[2];
    const float* pe  = (const float*)d_in[3];
    const float* Wq  = (const float*)d_in[5];
    const float* bq  = (const float*)d_in[6];
    const float* Wk  = (const float*)d_in[7];
    const float* bk  = (const float*)d_in[8];
    const float* Wv  = (const float*)d_in[9];
    const float* bv  = (const float*)d_in[10];
    const float* Wd  = (const float*)d_in[11];
    const float* bd  = (const float*)d_in[12];

    float* out  = (float*)d_out;
    float* attn = out + (size_t)B_*S_*D_;

    float *Qp, *Kp, *Vp, *Ctx, *Rs;
    cudaGetSymbolAddress((void**)&Qp,  g_Q);
    cudaGetSymbolAddress((void**)&Kp,  g_K);
    cudaGetSymbolAddress((void**)&Vp,  g_V);
    cudaGetSymbolAddress((void**)&Ctx, g_ctx);
    cudaGetSymbolAddress((void**)&Rs,  g_rsinv);

    proj3<<<dim3(8, 64, 3), 256>>>(q, k, pe, v, Wq, Wk, Wv, Wd,
                                   bq, bk, bv, bd, Qp, Kp, Vp);

    size_t smA = (size_t)(128*68 + 64*68 + 128) * sizeof(uint32_t);
    cudaFuncSetAttribute(attn_rowsum, cudaFuncAttributeMaxDynamicSharedMemorySize, (int)smA);
    attn_rowsum<<<dim3(16, BH), 256, smA>>>(Qp, Kp, Rs);

    size_t smB = (size_t)(128*68 + 64*68 + 128*68 + 64*68 + 128) * sizeof(uint32_t);
    cudaFuncSetAttribute(attn_pv, cudaFuncAttributeMaxDynamicSharedMemorySize, (int)smB);
    attn_pv<<<dim3(16, BH), 256, smB>>>(Qp, Kp, Vp, Rs, attn, Ctx);

    gemm_out<<<dim3(8, 64), 256>>>(Ctx, Wd, bd, out);
}

// round 7
// speedup vs baseline: 1.3169x; 1.3169x over previous
#include <cuda_runtime.h>
#include <cstdint>
#include <cstddef>

#define B_  4
#define S_  2048
#define D_  512
#define H_  8
#define DEPTH 64
#define BH  (B_*H_)

// ---------------- scratch (no allocations allowed) ----------------
__device__ float g_Q[(size_t)BH*S_*DEPTH];    // Q'  head-split (bh, s, d)
__device__ float g_K[(size_t)BH*S_*DEPTH];    // K'' = k@Wk + pos@Wd (head-split)
__device__ float g_V[(size_t)BH*S_*DEPTH];    // V'  head-split
__device__ float g_ctx[(size_t)B_*S_*D_];     // ctx in (B,S,D) layout
__device__ float g_rsinv[(size_t)BH*S_];      // 1/rowsum

// ---------------- tf32 helpers ----------------
__device__ __forceinline__ uint32_t f2tf(float x){
    uint32_t u; asm("cvt.rna.tf32.f32 %0, %1;" : "=r"(u) : "f"(x)); return u;
}
__device__ __forceinline__ uint4 tf4(float4 v){
    return make_uint4(f2tf(v.x), f2tf(v.y), f2tf(v.z), f2tf(v.w));
}
__device__ __forceinline__ void mma8(float c[4], uint32_t a0,uint32_t a1,uint32_t a2,uint32_t a3,
                                     uint32_t b0,uint32_t b1){
    asm volatile("mma.sync.aligned.m16n8k8.row.col.f32.tf32.tf32.f32 "
        "{%0,%1,%2,%3}, {%4,%5,%6,%7}, {%8,%9}, {%0,%1,%2,%3};"
        : "+f"(c[0]),"+f"(c[1]),"+f"(c[2]),"+f"(c[3])
        : "r"(a0),"r"(a1),"r"(a2),"r"(a3),"r"(b0),"r"(b1));
}

// ---------------- shared GEMM core (projections / output proj) ----------------
__device__ __forceinline__ void gemm_core(
    const float* __restrict__ A1, const float* __restrict__ B1, const float* __restrict__ bias1,
    const float* __restrict__ A2, const float* __restrict__ B2, const float* __restrict__ bias2,
    float* __restrict__ C, int split, int m0, int n0,
    uint32_t (*As)[36], uint32_t (*Bs)[72])
{
    int tid = threadIdx.x;
    int lane = tid & 31, wid = tid >> 5;
    int g = lane >> 2, tg = lane & 3;
    int wm = wid & 3, wn = wid >> 2;          // 4x2 warps -> CTA tile 128x64

    float acc[2][4][4];
    #pragma unroll
    for (int i=0;i<2;i++)
        #pragma unroll
        for (int j=0;j<4;j++)
            #pragma unroll
            for (int r=0;r<4;r++) acc[i][j][r]=0.f;

    const int ntile = A2 ? 32 : 16;
    float4 ra[4]; float4 rb[2];
    auto ldg_tile = [&](int t){
        const float* A  = (t >= 16) ? A2 : A1;
        const float* Bm = (t >= 16) ? B2 : B1;
        int k0 = (t & 15) * 32;
        #pragma unroll
        for (int i=0;i<4;i++){
            int e = tid + i*256; int r = e>>3, c = (e&7)*4;
            ra[i] = *(const float4*)(A + (size_t)(m0+r)*512 + k0 + c);
        }
        #pragma unroll
        for (int i=0;i<2;i++){
            int e = tid + i*256; int r = e>>4, c = (e&15)*4;
            rb[i] = *(const float4*)(Bm + (size_t)(k0+r)*512 + n0 + c);
        }
    };

    ldg_tile(0);
    for (int t = 0; t < ntile; t++){
        #pragma unroll
        for (int i=0;i<4;i++){
            int e = tid + i*256; int r = e>>3, c = (e&7)*4;
            *(uint4*)&As[r][c] = tf4(ra[i]);
        }
        #pragma unroll
        for (int i=0;i<2;i++){
            int e = tid + i*256; int r = e>>4, c = (e&15)*4;
            *(uint4*)&Bs[r][c] = tf4(rb[i]);
        }
        __syncthreads();
        if (t+1 < ntile) ldg_tile(t+1);
        #pragma unroll
        for (int kk=0; kk<32; kk+=8){
            uint32_t af[2][4];
            #pragma unroll
            for (int mi=0;mi<2;mi++){
                int rb_ = wm*32 + mi*16;
                af[mi][0]=As[rb_+g  ][kk+tg  ];
                af[mi][1]=As[rb_+g+8][kk+tg  ];
                af[mi][2]=As[rb_+g  ][kk+tg+4];
                af[mi][3]=As[rb_+g+8][kk+tg+4];
            }
            #pragma unroll
            for (int ni=0;ni<4;ni++){
                int cb = wn*32 + ni*8 + g;
                uint32_t b0=Bs[kk+tg  ][cb];
                uint32_t b1=Bs[kk+tg+4][cb];
                mma8(acc[0][ni], af[0][0],af[0][1],af[0][2],af[0][3], b0,b1);
                mma8(acc[1][ni], af[1][0],af[1][1],af[1][2],af[1][3], b0,b1);
            }
        }
        __syncthreads();
    }

    #pragma unroll
    for (int mi=0;mi<2;mi++)
        #pragma unroll
        for (int ni=0;ni<4;ni++)
            #pragma unroll
            for (int half=0; half<2; half++){
                int row = m0 + wm*32 + mi*16 + g + half*8;
                int col = n0 + wn*32 + ni*8 + tg*2;
                float b0v = bias1[col]   + (bias2 ? bias2[col]   : 0.f);
                float b1v = bias1[col+1] + (bias2 ? bias2[col+1] : 0.f);
                float v0 = acc[mi][ni][half*2+0] + b0v;
                float v1 = acc[mi][ni][half*2+1] + b1v;
                size_t idx;
                if (split){
                    int b = row >> 11, s = row & 2047;
                    int h = col >> 6,  d = col & 63;
                    idx = (((size_t)(b*H_ + h))*S_ + s)*DEPTH + d;
                } else {
                    idx = (size_t)row*512 + col;
                }
                *(float2*)(C + idx) = make_float2(v0, v1);
            }
}

// z=0: Q'=q@Wq+bq   z=1: K''=k@Wk+pe@Wd+bk+bd   z=2: V'=v@Wv+bv
__global__ __launch_bounds__(256, 3)
void proj3(const float* q, const float* k, const float* pe, const float* v,
           const float* Wq, const float* Wk, const float* Wv, const float* Wd,
           const float* bq, const float* bk, const float* bv, const float* bd,
           float* Qp, float* Kp, float* Vp)
{
    __shared__ uint32_t As[128][36];
    __shared__ uint32_t Bs[32][72];
    int m0 = blockIdx.y*128, n0 = blockIdx.x*64;
    if (blockIdx.z == 0)
        gemm_core(q, Wq, bq, nullptr,nullptr,nullptr, Qp, 1, m0,n0, As,Bs);
    else if (blockIdx.z == 1)
        gemm_core(k, Wk, bk, pe, Wd, bd, Kp, 1, m0,n0, As,Bs);
    else
        gemm_core(v, Wv, bv, nullptr,nullptr,nullptr, Vp, 1, m0,n0, As,Bs);
}

__global__ __launch_bounds__(256, 3)
void gemm_out(const float* __restrict__ A, const float* __restrict__ Bm,
              const float* __restrict__ bias, float* __restrict__ C)
{
    __shared__ uint32_t As[128][36];
    __shared__ uint32_t Bs[32][72];
    gemm_core(A, Bm, bias, nullptr,nullptr,nullptr, C, 0,
              blockIdx.y*128, blockIdx.x*64, As, Bs);
}

// ---------------- pass 1: rowsum of exp(logits) ----------------
__global__ __launch_bounds__(256, 3)
void attn_rowsum(const float* __restrict__ Q, const float* __restrict__ Kp,
                 float* __restrict__ rsinv)
{
    extern __shared__ uint32_t sm1[];
    uint32_t (*Qs)[68] = (uint32_t(*)[68])sm1;                 // 128x68 tf32
    uint32_t (*Ks)[68] = (uint32_t(*)[68])(sm1 + 128*68);      // 64x68 tf32
    float *rs = (float*)(sm1 + 128*68 + 64*68);                // 128

    int tid = threadIdx.x;
    int lane = tid & 31, wid = tid >> 5;
    int g = lane >> 2, tg = lane & 3;
    int wm = wid & 3, wn = wid >> 2;
    int bh = blockIdx.y;
    int s0 = blockIdx.x * 128;

    const float* Qb = Q  + ((size_t)bh*S_ + s0)*DEPTH;
    const float* Kb = Kp +  (size_t)bh*S_*DEPTH;

    #pragma unroll
    for (int i=0;i<8;i++){
        int e = tid + i*256;
        int r = e>>4, c = (e&15)*4;
        float4 v = *(const float4*)(Qb + (size_t)r*DEPTH + c);
        *(uint4*)&Qs[r][c] = tf4(v);
    }
    if (tid < 128) rs[tid] = 0.f;
    __syncthreads();

    float4 kr[4];
    auto ldgK = [&](int t0){
        #pragma unroll
        for (int i=0;i<4;i++){
            int e = tid + i*256;
            int r = e>>4, c = (e&15)*4;
            kr[i] = *(const float4*)(Kb + (size_t)(t0+r)*DEPTH + c);
        }
    };
    ldgK(0);

    float rowacc[4] = {0.f,0.f,0.f,0.f};

    for (int t0 = 0; t0 < S_; t0 += 64){
        #pragma unroll
        for (int i=0;i<4;i++){
            int e = tid + i*256;
            int r = e>>4, c = (e&15)*4;
            *(uint4*)&Ks[r][c] = tf4(kr[i]);
        }
        __syncthreads();
        if (t0 + 64 < S_) ldgK(t0 + 64);

        float acc[2][4][4];
        #pragma unroll
        for (int i=0;i<2;i++)
            #pragma unroll
            for (int j=0;j<4;j++)
                #pragma unroll
                for (int r=0;r<4;r++) acc[i][j][r]=0.f;

        #pragma unroll
        for (int kk=0; kk<64; kk+=8){
            uint32_t af[2][4];
            #pragma unroll
            for (int mi=0;mi<2;mi++){
                int rb = wm*32 + mi*16;
                af[mi][0]=Qs[rb+g  ][kk+tg  ];
                af[mi][1]=Qs[rb+g+8][kk+tg  ];
                af[mi][2]=Qs[rb+g  ][kk+tg+4];
                af[mi][3]=Qs[rb+g+8][kk+tg+4];
            }
            #pragma unroll
            for (int ni=0;ni<4;ni++){
                int cb = wn*32 + ni*8 + g;        // t index
                uint32_t b0=Ks[cb][kk+tg  ];
                uint32_t b1=Ks[cb][kk+tg+4];
                mma8(acc[0][ni], af[0][0],af[0][1],af[0][2],af[0][3], b0,b1);
                mma8(acc[1][ni], af[1][0],af[1][1],af[1][2],af[1][3], b0,b1);
            }
        }
        #pragma unroll
        for (int mi=0;mi<2;mi++)
            #pragma unroll
            for (int ni=0;ni<4;ni++)
                #pragma unroll
                for (int r2=0;r2<4;r2++)
                    rowacc[mi*2 + (r2>>1)] += __expf(acc[mi][ni][r2]*0.125f);
        __syncthreads();   // before Ks is overwritten
    }

    #pragma unroll
    for (int i=0;i<4;i++){
        float v = rowacc[i];
        v += __shfl_xor_sync(0xffffffffu, v, 1);
        v += __shfl_xor_sync(0xffffffffu, v, 2);
        if (tg == 0){
            int row = wm*32 + (i>>1)*16 + g + (i&1)*8;
            atomicAdd(&rs[row], v);
        }
    }
    __syncthreads();
    if (tid < 128) rsinv[(size_t)bh*S_ + s0 + tid] = 1.0f / rs[tid];
}

// ---------------- pass 2: attn write + ctx = attn @ V ----------------
__global__ __launch_bounds__(256)
void attn_pv(const float* __restrict__ Q, const float* __restrict__ Kp,
             const float* __restrict__ V, const float* __restrict__ rsinv,
             float* __restrict__ attn, float* __restrict__ ctx)
{
    extern __shared__ uint32_t sm2[];
    uint32_t (*Qs)[68] = (uint32_t(*)[68])sm2;                          // 128x68
    uint32_t (*Ks)[68] = (uint32_t(*)[68])(sm2 + 128*68);               // 64x68
    uint32_t (*Ps)[68] = (uint32_t(*)[68])(sm2 + 128*68 + 64*68);       // 128x68
    uint32_t (*Vs)[72] = (uint32_t(*)[72])(sm2 + 128*68 + 64*68 + 128*68); // 64x72
    float *rsv = (float*)(sm2 + 128*68 + 64*68 + 128*68 + 64*72);       // 128

    int tid = threadIdx.x;
    int lane = tid & 31, wid = tid >> 5;
    int g = lane >> 2, tg = lane & 3;
    int wm = wid & 3, wn = wid >> 2;
    int bh = blockIdx.y;
    int s0 = blockIdx.x * 128;

    const float* Qb = Q  + ((size_t)bh*S_ + s0)*DEPTH;
    const float* Kb = Kp +  (size_t)bh*S_*DEPTH;
    const float* Vb = V  +  (size_t)bh*S_*DEPTH;

    #pragma unroll
    for (int i=0;i<8;i++){
        int e = tid + i*256;
        int r = e>>4, c = (e&15)*4;
        float4 v = *(const float4*)(Qb + (size_t)r*DEPTH + c);
        *(uint4*)&Qs[r][c] = tf4(v);
    }
    if (tid < 128) rsv[tid] = rsinv[(size_t)bh*S_ + s0 + tid];
    __syncthreads();

    float4 kr[4], vr[4];
    auto ldgKV = [&](int t0){
        #pragma unroll
        for (int i=0;i<4;i++){
            int e = tid + i*256;
            int r = e>>4, c = (e&15)*4;
            kr[i] = *(const float4*)(Kb + (size_t)(t0+r)*DEPTH + c);
            vr[i] = *(const float4*)(Vb + (size_t)(t0+r)*DEPTH + c);
        }
    };
    ldgKV(0);

    float octx[2][4][4];
    #pragma unroll
    for (int i=0;i<2;i++)
        #pragma unroll
        for (int j=0;j<4;j++)
            #pragma unroll
            for (int r=0;r<4;r++) octx[i][j][r]=0.f;

    for (int t0 = 0; t0 < S_; t0 += 64){
        #pragma unroll
        for (int i=0;i<4;i++){
            int e = tid + i*256;
            int r = e>>4, c = (e&15)*4;
            *(uint4*)&Ks[r][c] = tf4(kr[i]);
            *(uint4*)&Vs[r][c] = tf4(vr[i]);
        }
        __syncthreads();
        if (t0 + 64 < S_) ldgKV(t0 + 64);

        float acc[2][4][4];
        #pragma unroll
        for (int i=0;i<2;i++)
            #pragma unroll
            for (int j=0;j<4;j++)
                #pragma unroll
                for (int r=0;r<4;r++) acc[i][j][r]=0.f;

        // logits = Q @ K''^T
        #pragma unroll
        for (int kk=0; kk<64; kk+=8){
            uint32_t af[2][4];
            #pragma unroll
            for (int mi=0;mi<2;mi++){
                int rb = wm*32 + mi*16;
                af[mi][0]=Qs[rb+g  ][kk+tg  ];
                af[mi][1]=Qs[rb+g+8][kk+tg  ];
                af[mi][2]=Qs[rb+g  ][kk+tg+4];
                af[mi][3]=Qs[rb+g+8][kk+tg+4];
            }
            #pragma unroll
            for (int ni=0;ni<4;ni++){
                int cb = wn*32 + ni*8 + g;
                uint32_t b0=Ks[cb][kk+tg  ];
                uint32_t b1=Ks[cb][kk+tg+4];
                mma8(acc[0][ni], af[0][0],af[0][1],af[0][2],af[0][3], b0,b1);
                mma8(acc[1][ni], af[1][0],af[1][1],af[1][2],af[1][3], b0,b1);
            }
        }

        // p = exp(l/8) / rowsum ; write attn (float) + stage P (tf32)
        #pragma unroll
        for (int mi=0;mi<2;mi++){
            int r0 = wm*32 + mi*16 + g;
            float inv0 = rsv[r0], inv1 = rsv[r0+8];
            #pragma unroll
            for (int ni=0;ni<4;ni++){
                acc[mi][ni][0] = __expf(acc[mi][ni][0]*0.125f)*inv0;
                acc[mi][ni][1] = __expf(acc[mi][ni][1]*0.125f)*inv0;
                acc[mi][ni][2] = __expf(acc[mi][ni][2]*0.125f)*inv1;
                acc[mi][ni][3] = __expf(acc[mi][ni][3]*0.125f)*inv1;
            }
        }
        #pragma unroll
        for (int mi=0;mi<2;mi++)
            #pragma unroll
            for (int ni=0;ni<4;ni++)
                #pragma unroll
                for (int half=0; half<2; half++){
                    int rloc = wm*32 + mi*16 + g + half*8;
                    int cloc = wn*32 + ni*8 + tg*2;
                    float2 v2 = make_float2(acc[mi][ni][half*2], acc[mi][ni][half*2+1]);
                    *(uint2*)&Ps[rloc][cloc] = make_uint2(f2tf(v2.x), f2tf(v2.y));
                    size_t aidx = ((size_t)bh*S_ + s0 + rloc)*S_ + t0 + cloc;
                    *(float2*)(attn + aidx) = v2;
                }
        __syncthreads();   // P complete before PV mma

        // ctx += P @ V
        #pragma unroll
        for (int kk=0; kk<64; kk+=8){
            uint32_t af[2][4];
            #pragma unroll
            for (int mi=0;mi<2;mi++){
                int rb = wm*32 + mi*16;
                af[mi][0]=Ps[rb+g  ][kk+tg  ];
                af[mi][1]=Ps[rb+g+8][kk+tg  ];
                af[mi][2]=Ps[rb+g  ][kk+tg+4];
                af[mi][3]=Ps[rb+g+8][kk+tg+4];
            }
            #pragma unroll
            for (int ni=0;ni<4;ni++){
                int cb = wn*32 + ni*8 + g;       // d index
                uint32_t b0=Vs[kk+tg  ][cb];
                uint32_t b1=Vs[kk+tg+4][cb];
                mma8(octx[0][ni], af[0][0],af[0][1],af[0][2],af[0][3], b0,b1);
                mma8(octx[1][ni], af[1][0],af[1][1],af[1][2],af[1][3], b0,b1);
            }
        }
        __syncthreads();   // before Ks/Vs overwritten next iter
    }

    // write ctx in (B,S,D) layout
    int b = bh >> 3, h = bh & 7;
    #pragma unroll
    for (int mi=0;mi<2;mi++)
        #pragma unroll
        for (int ni=0;ni<4;ni++)
            #pragma unroll
            for (int half=0; half<2; half++){
                int row = s0 + wm*32 + mi*16 + g + half*8;
                int col = h*64 + wn*32 + ni*8 + tg*2;
                float2 v2 = make_float2(octx[mi][ni][half*2], octx[mi][ni][half*2+1]);
                *(float2*)(ctx + ((size_t)b*S_ + row)*D_ + col) = v2;
            }
}

// ---------------- launch ----------------
extern "C" void kernel_launch(void* const* d_in, const int* in_sizes, int n_in,
                              void* d_out, int out_size)
{
    const float* q   = (const float*)d_in[0];
    const float* k   = (const float*)d_in[1];
    const float* v   = (const float*)d_in[2];
    const float* pe  = (const float*)d_in[3];
    // d_in[4] = mask (unused by reference)
    const float* Wq  = (const float*)d_in[5];
    const float* bq  = (const float*)d_in[6];
    const float* Wk  = (const float*)d_in[7];
    const float* bk  = (const float*)d_in[8];
    const float* Wv  = (const float*)d_in[9];
    const float* bv  = (const float*)d_in[10];
    const float* Wd  = (const float*)d_in[11];
    const float* bd  = (const float*)d_in[12];

    float* out  = (float*)d_out;                       // (B,S,D)
    float* attn = out + (size_t)B_*S_*D_;              // (B,H,S,S)

    float *Qp, *Kp, *Vp, *Ctx, *Rs;
    cudaGetSymbolAddress((void**)&Qp,  g_Q);
    cudaGetSymbolAddress((void**)&Kp,  g_K);
    cudaGetSymbolAddress((void**)&Vp,  g_V);
    cudaGetSymbolAddress((void**)&Ctx, g_ctx);
    cudaGetSymbolAddress((void**)&Rs,  g_rsinv);

    // Q', K''(=k@Wk+pe@Wd), V' in one launch
    proj3<<<dim3(8, 64, 3), 256>>>(q, k, pe, v, Wq, Wk, Wv, Wd,
                                   bq, bk, bv, bd, Qp, Kp, Vp);

    size_t smA = (size_t)(128*68 + 64*68 + 128) * sizeof(uint32_t);
    cudaFuncSetAttribute(attn_rowsum, cudaFuncAttributeMaxDynamicSharedMemorySize, (int)smA);
    attn_rowsum<<<dim3(16, BH), 256, smA>>>(Qp, Kp, Rs);

    size_t smB = (size_t)(128*68 + 64*68 + 128*68 + 64*72 + 128) * sizeof(uint32_t);
    cudaFuncSetAttribute(attn_pv, cudaFuncAttributeMaxDynamicSharedMemorySize, (int)smB);
    attn_pv<<<dim3(16, BH), 256, smB>>>(Qp, Kp, Vp, Rs, attn, Ctx);

    gemm_out<<<dim3(8, 64), 256>>>(Ctx, Wd, bd, out);
}